// round 2
// baseline (speedup 1.0000x reference)
#include <cuda_runtime.h>
#include <math.h>

#define BATCH 8
#define SEQ 1024
#define DMODEL 768
#define NH 12
#define HD 64
#define ATTN_SCALE 0.125f

#define QT_STRIDE 132
#define KV_STRIDE 68

// Scratch (allowed: __device__ globals, no runtime allocation)
__device__ float g_q[BATCH * NH * SEQ * HD];
__device__ float g_k[BATCH * NH * SEQ * HD];
__device__ float g_v[BATCH * NH * SEQ * HD];
__device__ float g_ctx[BATCH * NH * SEQ * HD];

// ---------------------------------------------------------------------------
// QKV GEMM: C[8192,2304] = A[8192,768] @ W[768,2304] + bias, scattered into
// q/k/v arrays with layout [B, H, S, HD].
// 128x128 tile, BK=16, 256 threads, 8x8 microtile, warp tile 32(m)x64(n).
// ---------------------------------------------------------------------------
__global__ __launch_bounds__(256) void qkv_gemm_kernel(
    const float* __restrict__ A, const float* __restrict__ W,
    const float* __restrict__ bias)
{
    __shared__ float Ats[16 * 128];   // A transposed: [k][m]
    __shared__ float Bs[16 * 128];    // B natural:    [k][n]

    const int tid = threadIdx.x;
    const int nb = blockIdx.x * 128;
    const int mb = blockIdx.y * 128;

    const int warp = tid >> 5, lane = tid & 31;
    const int wm = warp & 3, wn = warp >> 2;   // 4 x 2 warp grid
    const int lm = lane & 3, ln = lane >> 2;   // 4 x 8 lane grid
    const int ri = wm * 32 + lm * 8;           // row offset in tile
    const int cj = wn * 64 + ln * 8;           // col offset in tile

    float acc[8][8];
#pragma unroll
    for (int r = 0; r < 8; ++r)
#pragma unroll
        for (int c = 0; c < 8; ++c) acc[r][c] = 0.f;

    for (int kt = 0; kt < DMODEL; kt += 16) {
#pragma unroll
        for (int it = 0; it < 2; ++it) {
            int g = it * 256 + tid;
            int row = g >> 2, k4 = (g & 3) << 2;
            float4 v = *reinterpret_cast<const float4*>(
                &A[(size_t)(mb + row) * DMODEL + kt + k4]);
            Ats[(k4 + 0) * 128 + row] = v.x;
            Ats[(k4 + 1) * 128 + row] = v.y;
            Ats[(k4 + 2) * 128 + row] = v.z;
            Ats[(k4 + 3) * 128 + row] = v.w;
        }
#pragma unroll
        for (int it = 0; it < 2; ++it) {
            int g = it * 256 + tid;
            int k = g >> 5, n4 = (g & 31) << 2;
            *reinterpret_cast<float4*>(&Bs[k * 128 + n4]) =
                *reinterpret_cast<const float4*>(
                    &W[(size_t)(kt + k) * (3 * DMODEL) + nb + n4]);
        }
        __syncthreads();
#pragma unroll
        for (int k = 0; k < 16; ++k) {
            float a[8], b[8];
            *reinterpret_cast<float4*>(&a[0]) =
                *reinterpret_cast<const float4*>(&Ats[k * 128 + ri]);
            *reinterpret_cast<float4*>(&a[4]) =
                *reinterpret_cast<const float4*>(&Ats[k * 128 + ri + 4]);
            *reinterpret_cast<float4*>(&b[0]) =
                *reinterpret_cast<const float4*>(&Bs[k * 128 + cj]);
            *reinterpret_cast<float4*>(&b[4]) =
                *reinterpret_cast<const float4*>(&Bs[k * 128 + cj + 4]);
#pragma unroll
            for (int r = 0; r < 8; ++r)
#pragma unroll
                for (int c = 0; c < 8; ++c)
                    acc[r][c] = fmaf(a[r], b[c], acc[r][c]);
        }
        __syncthreads();
    }

    // Epilogue: scatter into q/k/v [B,H,S,HD]. Column chunk of 8 never
    // crosses a 64 (head) or 768 (which) boundary since cj % 8 == 0.
    const int n0 = nb + cj;
    const int which = n0 / DMODEL;
    const int rem = n0 - which * DMODEL;
    const int h = rem >> 6, d0 = rem & 63;
    float* dst = (which == 0) ? g_q : ((which == 1) ? g_k : g_v);
    float bb[8];
#pragma unroll
    for (int c = 0; c < 8; ++c) bb[c] = bias[n0 + c];
#pragma unroll
    for (int r = 0; r < 8; ++r) {
        int m = mb + ri + r;
        int b = m >> 10, s = m & 1023;
        float* p = dst + (((size_t)(b * NH + h) * SEQ + s) * HD + d0);
        *reinterpret_cast<float4*>(p) = make_float4(
            acc[r][0] + bb[0], acc[r][1] + bb[1],
            acc[r][2] + bb[2], acc[r][3] + bb[3]);
        *reinterpret_cast<float4*>(p + 4) = make_float4(
            acc[r][4] + bb[4], acc[r][5] + bb[5],
            acc[r][6] + bb[6], acc[r][7] + bb[7]);
    }
}

// ---------------------------------------------------------------------------
// Flash attention: per block one (b, h) and 128 query rows; stream KV in
// 64-row tiles with online softmax. fp32 throughout. Writes ctx [B,H,S,HD].
// 128 threads; S-tile 128x64 with 8x8 microtiles (warp tile 32x64).
// ---------------------------------------------------------------------------
__global__ __launch_bounds__(128) void attn_kernel()
{
    extern __shared__ float sm[];
    float* Qt = sm;                         // [64][QT_STRIDE]  Q transposed [d][i]
    float* KV = Qt + 64 * QT_STRIDE;        // [64][KV_STRIDE]  Kt [d][j], then V [j][d]
    float* Pt = KV + 64 * KV_STRIDE;        // [64][128]        P transposed [j][i]
    float* alpha_s = Pt + 64 * 128;         // [128]
    float* linv = alpha_s + 128;            // [128]

    const int tid = threadIdx.x;
    const int qb = blockIdx.x * 128;
    const int h = blockIdx.y, b = blockIdx.z;
    const size_t base = ((size_t)(b * NH + h)) * SEQ * HD;
    const float* Qg = g_q + base;
    const float* Kg = g_k + base;
    const float* Vg = g_v + base;

    const int warp = tid >> 5, lane = tid & 31;
    const int lm = lane & 3, ln = lane >> 2;
    const int i0 = warp * 32 + lm * 8;      // query-row offset (0..120)
    const int j0 = ln * 8;                  // kv-col / headdim offset (0..56)

    // Load Q tile [128][64] transposed
#pragma unroll
    for (int it = 0; it < 16; ++it) {
        int g = it * 128 + tid;
        int i = g >> 4, d4 = (g & 15) << 2;
        float4 v = *reinterpret_cast<const float4*>(&Qg[(size_t)(qb + i) * HD + d4]);
        Qt[(d4 + 0) * QT_STRIDE + i] = v.x;
        Qt[(d4 + 1) * QT_STRIDE + i] = v.y;
        Qt[(d4 + 2) * QT_STRIDE + i] = v.z;
        Qt[(d4 + 3) * QT_STRIDE + i] = v.w;
    }

    float oacc[8][8];
#pragma unroll
    for (int r = 0; r < 8; ++r)
#pragma unroll
        for (int c = 0; c < 8; ++c) oacc[r][c] = 0.f;
    float m_run = -1e30f, l_run = 0.f;

    for (int kt = 0; kt < SEQ; kt += 64) {
        // Load K tile [64][64] transposed into KV
#pragma unroll
        for (int it = 0; it < 8; ++it) {
            int g = it * 128 + tid;
            int j = g >> 4, d4 = (g & 15) << 2;
            float4 v = *reinterpret_cast<const float4*>(&Kg[(size_t)(kt + j) * HD + d4]);
            KV[(d4 + 0) * KV_STRIDE + j] = v.x;
            KV[(d4 + 1) * KV_STRIDE + j] = v.y;
            KV[(d4 + 2) * KV_STRIDE + j] = v.z;
            KV[(d4 + 3) * KV_STRIDE + j] = v.w;
        }
        __syncthreads();

        // S = Q K^T (128x64)
        float sacc[8][8];
#pragma unroll
        for (int r = 0; r < 8; ++r)
#pragma unroll
            for (int c = 0; c < 8; ++c) sacc[r][c] = 0.f;
#pragma unroll
        for (int d = 0; d < 64; ++d) {
            float qa[8], kb[8];
            *reinterpret_cast<float4*>(&qa[0]) =
                *reinterpret_cast<const float4*>(&Qt[d * QT_STRIDE + i0]);
            *reinterpret_cast<float4*>(&qa[4]) =
                *reinterpret_cast<const float4*>(&Qt[d * QT_STRIDE + i0 + 4]);
            *reinterpret_cast<float4*>(&kb[0]) =
                *reinterpret_cast<const float4*>(&KV[d * KV_STRIDE + j0]);
            *reinterpret_cast<float4*>(&kb[4]) =
                *reinterpret_cast<const float4*>(&KV[d * KV_STRIDE + j0 + 4]);
#pragma unroll
            for (int r = 0; r < 8; ++r)
#pragma unroll
                for (int c = 0; c < 8; ++c)
                    sacc[r][c] = fmaf(qa[r], kb[c], sacc[r][c]);
        }
        // Write S^T into Pt[j][i]
#pragma unroll
        for (int c = 0; c < 8; ++c) {
            *reinterpret_cast<float4*>(&Pt[(j0 + c) * 128 + i0]) =
                make_float4(sacc[0][c], sacc[1][c], sacc[2][c], sacc[3][c]);
            *reinterpret_cast<float4*>(&Pt[(j0 + c) * 128 + i0 + 4]) =
                make_float4(sacc[4][c], sacc[5][c], sacc[6][c], sacc[7][c]);
        }
        __syncthreads();

        // Load V tile [64][64] natural into KV (K data dead now)
#pragma unroll
        for (int it = 0; it < 8; ++it) {
            int g = it * 128 + tid;
            int j = g >> 4, d4 = (g & 15) << 2;
            *reinterpret_cast<float4*>(&KV[j * KV_STRIDE + d4]) =
                *reinterpret_cast<const float4*>(&Vg[(size_t)(kt + j) * HD + d4]);
        }

        // Online softmax: thread tid owns query row tid (column tid of Pt)
        {
            float tmax = -1e30f;
#pragma unroll 16
            for (int j = 0; j < 64; ++j)
                tmax = fmaxf(tmax, Pt[j * 128 + tid]);
            float m_new = fmaxf(m_run, tmax * ATTN_SCALE);
            float a = __expf(m_run - m_new);
            float sum = 0.f;
#pragma unroll 16
            for (int j = 0; j < 64; ++j) {
                float p = __expf(fmaf(Pt[j * 128 + tid], ATTN_SCALE, -m_new));
                Pt[j * 128 + tid] = p;
                sum += p;
            }
            l_run = fmaf(l_run, a, sum);
            m_run = m_new;
            alpha_s[tid] = a;
        }
        __syncthreads();

        // Rescale O then accumulate O += P V
#pragma unroll
        for (int r = 0; r < 8; ++r) {
            float a = alpha_s[i0 + r];
#pragma unroll
            for (int c = 0; c < 8; ++c) oacc[r][c] *= a;
        }
#pragma unroll
        for (int j = 0; j < 64; ++j) {
            float p[8], vv[8];
            *reinterpret_cast<float4*>(&p[0]) =
                *reinterpret_cast<const float4*>(&Pt[j * 128 + i0]);
            *reinterpret_cast<float4*>(&p[4]) =
                *reinterpret_cast<const float4*>(&Pt[j * 128 + i0 + 4]);
            *reinterpret_cast<float4*>(&vv[0]) =
                *reinterpret_cast<const float4*>(&KV[j * KV_STRIDE + j0]);
            *reinterpret_cast<float4*>(&vv[4]) =
                *reinterpret_cast<const float4*>(&KV[j * KV_STRIDE + j0 + 4]);
#pragma unroll
            for (int r = 0; r < 8; ++r)
#pragma unroll
                for (int c = 0; c < 8; ++c)
                    oacc[r][c] = fmaf(p[r], vv[c], oacc[r][c]);
        }
        __syncthreads();
    }

    linv[tid] = 1.f / l_run;
    __syncthreads();

    float* Og = g_ctx + base;
#pragma unroll
    for (int r = 0; r < 8; ++r) {
        int i = i0 + r;
        float inv = linv[i];
        *reinterpret_cast<float4*>(&Og[(size_t)(qb + i) * HD + j0]) =
            make_float4(oacc[r][0] * inv, oacc[r][1] * inv,
                        oacc[r][2] * inv, oacc[r][3] * inv);
        *reinterpret_cast<float4*>(&Og[(size_t)(qb + i) * HD + j0 + 4]) =
            make_float4(oacc[r][4] * inv, oacc[r][5] * inv,
                        oacc[r][6] * inv, oacc[r][7] * inv);
    }
}

// ---------------------------------------------------------------------------
// Proj GEMM: out[8192,768] = ctx[8192,768] @ Wp[768,768] + bias.
// ctx is gathered from [B,H,S,HD] layout.
// ---------------------------------------------------------------------------
__global__ __launch_bounds__(256) void proj_gemm_kernel(
    const float* __restrict__ W, const float* __restrict__ bias,
    float* __restrict__ out)
{
    __shared__ float Ats[16 * 128];
    __shared__ float Bs[16 * 128];

    const int tid = threadIdx.x;
    const int nb = blockIdx.x * 128;
    const int mb = blockIdx.y * 128;

    const int warp = tid >> 5, lane = tid & 31;
    const int wm = warp & 3, wn = warp >> 2;
    const int lm = lane & 3, ln = lane >> 2;
    const int ri = wm * 32 + lm * 8;
    const int cj = wn * 64 + ln * 8;

    float acc[8][8];
#pragma unroll
    for (int r = 0; r < 8; ++r)
#pragma unroll
        for (int c = 0; c < 8; ++c) acc[r][c] = 0.f;

    for (int kt = 0; kt < DMODEL; kt += 16) {
        const int hk = kt >> 6;       // head of this k-tile (tile never crosses)
        const int dk = kt & 63;
#pragma unroll
        for (int it = 0; it < 2; ++it) {
            int g = it * 256 + tid;
            int row = g >> 2, k4 = (g & 3) << 2;
            int m = mb + row;
            int b = m >> 10, s = m & 1023;
            float4 v = *reinterpret_cast<const float4*>(
                &g_ctx[(((size_t)(b * NH + hk) * SEQ + s) * HD) + dk + k4]);
            Ats[(k4 + 0) * 128 + row] = v.x;
            Ats[(k4 + 1) * 128 + row] = v.y;
            Ats[(k4 + 2) * 128 + row] = v.z;
            Ats[(k4 + 3) * 128 + row] = v.w;
        }
#pragma unroll
        for (int it = 0; it < 2; ++it) {
            int g = it * 256 + tid;
            int k = g >> 5, n4 = (g & 31) << 2;
            *reinterpret_cast<float4*>(&Bs[k * 128 + n4]) =
                *reinterpret_cast<const float4*>(
                    &W[(size_t)(kt + k) * DMODEL + nb + n4]);
        }
        __syncthreads();
#pragma unroll
        for (int k = 0; k < 16; ++k) {
            float a[8], b[8];
            *reinterpret_cast<float4*>(&a[0]) =
                *reinterpret_cast<const float4*>(&Ats[k * 128 + ri]);
            *reinterpret_cast<float4*>(&a[4]) =
                *reinterpret_cast<const float4*>(&Ats[k * 128 + ri + 4]);
            *reinterpret_cast<float4*>(&b[0]) =
                *reinterpret_cast<const float4*>(&Bs[k * 128 + cj]);
            *reinterpret_cast<float4*>(&b[4]) =
                *reinterpret_cast<const float4*>(&Bs[k * 128 + cj + 4]);
#pragma unroll
            for (int r = 0; r < 8; ++r)
#pragma unroll
                for (int c = 0; c < 8; ++c)
                    acc[r][c] = fmaf(a[r], b[c], acc[r][c]);
        }
        __syncthreads();
    }

    float bb[8];
#pragma unroll
    for (int c = 0; c < 8; ++c) bb[c] = bias[nb + cj + c];
#pragma unroll
    for (int r = 0; r < 8; ++r) {
        int m = mb + ri + r;
        float* p = out + (size_t)m * DMODEL + nb + cj;
        *reinterpret_cast<float4*>(p) = make_float4(
            acc[r][0] + bb[0], acc[r][1] + bb[1],
            acc[r][2] + bb[2], acc[r][3] + bb[3]);
        *reinterpret_cast<float4*>(p + 4) = make_float4(
            acc[r][4] + bb[4], acc[r][5] + bb[5],
            acc[r][6] + bb[6], acc[r][7] + bb[7]);
    }
}

extern "C" void kernel_launch(void* const* d_in, const int* in_sizes, int n_in,
                              void* d_out, int out_size)
{
    const float* hidden = (const float*)d_in[0];
    const float* w_qkv  = (const float*)d_in[1];
    const float* b_qkv  = (const float*)d_in[2];
    const float* w_proj = (const float*)d_in[3];
    const float* b_proj = (const float*)d_in[4];
    float* out = (float*)d_out;

    const size_t attn_smem =
        (size_t)(64 * QT_STRIDE + 64 * KV_STRIDE + 64 * 128 + 256) * sizeof(float);
    cudaFuncSetAttribute(attn_kernel,
                         cudaFuncAttributeMaxDynamicSharedMemorySize,
                         (int)attn_smem);

    qkv_gemm_kernel<<<dim3((3 * DMODEL) / 128, (BATCH * SEQ) / 128), 256>>>(
        hidden, w_qkv, b_qkv);
    attn_kernel<<<dim3(SEQ / 128, NH, BATCH), 128, attn_smem>>>();
    proj_gemm_kernel<<<dim3(DMODEL / 128, (BATCH * SEQ) / 128), 256>>>(
        w_proj, b_proj, out);
}